// round 8
// baseline (speedup 1.0000x reference)
#include <cuda_runtime.h>
#include <cstdint>

#define Hh 384
#define Ww 512
#define Bb 8
#define HW (Hh*Ww)              // 196608
#define NFULL (Bb*5*HW)         // 7864320
#define NSTEPS 200
#define TW 32
#define TH 16
#define EBLK 96                 // partial blocks per (mode,batch): 196608/96 = 2048 px/block

// ---------------- static scratch (no allocation allowed) ----------------
__device__ float g_bufA[NFULL];
__device__ float g_bufB[NFULL];
__device__ float g_K[2];
__device__ float g_part[2*Bb*EBLK*2];

// ---------------- threefry2x32, JAX-exact, c0 = 0, N independent lanes ----
template<int N>
__device__ __forceinline__ void tf_bitsN(uint32_t k0, uint32_t k1,
                                         const uint32_t* c, uint32_t* r)
{
    const uint32_t ks2 = k0 ^ k1 ^ 0x1BD11BDAu;
    uint32_t x0[N], x1[N];
#pragma unroll
    for (int i = 0; i < N; i++) { x0[i] = k0; x1[i] = c[i] + k1; }

    auto rnd = [&](int rot) {
#pragma unroll
        for (int i = 0; i < N; i++) {
            x0[i] += x1[i];
            x1[i] = __funnelshift_l(x1[i], x1[i], rot);
            x1[i] ^= x0[i];
        }
    };
    auto inj = [&](uint32_t i0, uint32_t i1) {
#pragma unroll
        for (int i = 0; i < N; i++) { x0[i] += i0; x1[i] += i1; }
    };

    rnd(13); rnd(15); rnd(26); rnd(6);  inj(k1,  ks2 + 1u);
    rnd(17); rnd(29); rnd(16); rnd(24); inj(ks2, k0  + 2u);
    rnd(13); rnd(15); rnd(26); rnd(6);  inj(k0,  k1  + 3u);
    rnd(17); rnd(29); rnd(16); rnd(24); inj(k1,  ks2 + 4u);
    rnd(13); rnd(15); rnd(26); rnd(6);  inj(ks2, k0  + 5u);

#pragma unroll
    for (int i = 0; i < N; i++) r[i] = x0[i] ^ x1[i];
}

// ------------- jax.random.normal: uniform(lo,1) -> sqrt(2)*erfinv --------
__device__ __forceinline__ float jax_normal(uint32_t bits)
{
    const float lo = __uint_as_float(0xBF7FFFFFu);      // nextafter(-1, 0)
    float f = __uint_as_float((bits >> 9) | 0x3F800000u) - 1.0f;  // [0,1)
    float u = fmaxf(lo, f * 2.0f + lo);                 // hi-lo rounds to 2.0f

    // XLA ErfInv f32 (Giles)
    float w = -log1pf(-u * u);
    float p;
    if (w < 5.0f) {
        w = w - 2.5f;
        p =          2.81022636e-08f;
        p = p * w +  3.43273939e-07f;
        p = p * w + -3.5233877e-06f;
        p = p * w + -4.39150654e-06f;
        p = p * w +  0.00021858087f;
        p = p * w + -0.00125372503f;
        p = p * w + -0.00417768164f;
        p = p * w +  0.246640727f;
        p = p * w +  1.50140941f;
    } else {
        w = sqrtf(w) - 3.0f;
        p =         -0.000200214257f;
        p = p * w +  0.000100950558f;
        p = p * w +  0.00134934322f;
        p = p * w + -0.00367342844f;
        p = p * w +  0.00573950773f;
        p = p * w + -0.0076224613f;
        p = p * w +  0.00943887047f;
        p = p * w +  1.00167406f;
        p = p * w +  2.83297682f;
    }
    return 1.41421356237309515f * (p * u);
}

__device__ __forceinline__ float noised_clip(float x, float n)
{
    float d = __fmul_rn(0.05f, n);
    return fminf(fmaxf(x + d, -1.0f), 1.0f);
}

// ---------------- K = exp(lw)/(H*W) ----------------
__global__ void k_init(const float* __restrict__ lw)
{
    g_K[0] = expf(lw[0]) / 196608.0f;
    g_K[1] = expf(lw[1]) / 196608.0f;
}

// ---------------- fused Langevin step: noise + analytic grad + update ----
__global__ void __launch_bounds__(TW*TH)
step_kernel(const float* __restrict__ src, float* __restrict__ dst,
            const float* __restrict__ input2, uint32_t k0, uint32_t k1)
{
    __shared__ float sf0[TH+2][TW+2];
    __shared__ float sf1[TH+2][TW+2];

    const int b  = blockIdx.z;
    const int h0 = blockIdx.y * TH;
    const int w0 = blockIdx.x * TW;
    const int tid = threadIdx.x;
    const int tx = tid & (TW-1), ty = tid / TW;
    const int base_b = b * 5 * HW;

    // fill flow tile + 1-halo: noised+clipped (halo noise recomputed; OOB -> 0, masked)
    for (int idx = tid; idx < (TH+2)*(TW+2); idx += TW*TH) {
        int hh = idx / (TW+2) - 1;
        int ww = idx - (hh+1)*(TW+2) - 1;
        int h = h0 + hh, w = w0 + ww;
        float y0 = 0.0f, y1 = 0.0f;
        if ((unsigned)h < (unsigned)Hh && (unsigned)w < (unsigned)Ww) {
            uint32_t ce[2];
            ce[0] = (uint32_t)(base_b + h*Ww + w);
            ce[1] = ce[0] + (uint32_t)HW;
            float xa = src[ce[0]], xb = src[ce[1]];
            uint32_t rb[2];
            tf_bitsN<2>(k0, k1, ce, rb);
            y0 = noised_clip(xa, jax_normal(rb[0]));
            y1 = noised_clip(xb, jax_normal(rb[1]));
        }
        sf0[hh+1][ww+1] = y0;
        sf1[hh+1][ww+1] = y1;
    }
    __syncthreads();

    const int h = h0 + ty, w = w0 + tx;
    const int pix = h*Ww + w;
    const float K0 = g_K[0], K1 = g_K[1];

    // ---- image channels: local data-term gradient ----
    {
        uint32_t ce[3]; float xv[3];
#pragma unroll
        for (int c = 0; c < 3; c++) {
            ce[c] = (uint32_t)(base_b + (2+c)*HW + pix);
            xv[c] = src[ce[c]];
        }
        uint32_t rb[3];
        tf_bitsN<3>(k0, k1, ce, rb);
        float yimg[3], diff[3], A = 0.0f;
#pragma unroll
        for (int c = 0; c < 3; c++) {
            float y = noised_clip(xv[c], jax_normal(rb[c]));
            yimg[c] = y;
            float i2    = input2[(b*3+c)*HW + pix];
            float img2p = ((i2*2.0f - 1.0f) + 1.0f) * 0.5f;
            float img1p = (y + 1.0f) * 0.5f;
            float d = img1p - img2p;
            diff[c] = d;
            A += d*d;
        }
        float cD = K0 * (0.5f / sqrtf(A + 1e-5f));
#pragma unroll
        for (int c = 0; c < 3; c++) {
            float g = cD * diff[c];             // == cD*(2*diff)*0.5 exactly
            g = fminf(fmaxf(g, -0.03f), 0.03f);
            float sg = __fmul_rn(10.0f, g);
            dst[ce[c]] = fminf(fmaxf(yimg[c] - sg, -1.0f), 1.0f);
        }
    }

    // ---- flow channels: smoothness-term stencil gradient ----
    {
        const int si = ty + 1, sj = tx + 1;
        const bool wp = (w < Ww-1), hp = (h < Hh-1);
        const bool wm = (w > 0),    hm = (h > 0);

        float c0  = sf0[si][sj],     c1  = sf1[si][sj];      // noised flow (unscaled)
        float f0  = c0*80.0f,        f1  = c1*80.0f;
        float f0r = sf0[si][sj+1]*80.0f,   f1r = sf1[si][sj+1]*80.0f;
        float f0d = sf0[si+1][sj]*80.0f,   f1d = sf1[si+1][sj]*80.0f;
        float f0l = sf0[si][sj-1]*80.0f,   f1l = sf1[si][sj-1]*80.0f;
        float f0u = sf0[si-1][sj]*80.0f,   f1u = sf1[si-1][sj]*80.0f;
        float f0dl= sf0[si+1][sj-1]*80.0f, f1dl= sf1[si+1][sj-1]*80.0f;
        float f0ur= sf0[si-1][sj+1]*80.0f, f1ur= sf1[si-1][sj+1]*80.0f;

        // R at (h, w)
        float dx0 = f0r - f0, dx1 = f1r - f1;
        float dy0 = f0d - f0, dy1 = f1d - f1;
        float Sc = (wp ? dx0*dx0 + dx1*dx1 : 0.0f)
                 + (hp ? dy0*dy0 + dy1*dy1 : 0.0f) + 1e-5f;
        float gAc = K1 * (0.5f / sqrtf(Sc));

        // R at (h, w-1): Bx always valid when wm; By valid iff hp
        float dxl0 = f0 - f0l,   dxl1 = f1 - f1l;
        float dyl0 = f0dl - f0l, dyl1 = f1dl - f1l;
        float Sl = (dxl0*dxl0 + dxl1*dxl1)
                 + (hp ? dyl0*dyl0 + dyl1*dyl1 : 0.0f) + 1e-5f;
        float gAl = K1 * (0.5f / sqrtf(Sl));

        // R at (h-1, w): By always valid when hm; Bx valid iff wp
        float dxu0 = f0ur - f0u, dxu1 = f1ur - f1u;
        float dyu0 = f0 - f0u,   dyu1 = f1 - f1u;
        float Su = (wp ? dxu0*dxu0 + dxu1*dxu1 : 0.0f)
                 + (dyu0*dyu0 + dyu1*dyu1) + 1e-5f;
        float gAu = K1 * (0.5f / sqrtf(Su));

        float g0 = 0.0f, g1 = 0.0f;
        if (wp) { g0 -= gAc*(2.0f*dx0);  g1 -= gAc*(2.0f*dx1);  }
        if (hp) { g0 -= gAc*(2.0f*dy0);  g1 -= gAc*(2.0f*dy1);  }
        if (wm) { g0 += gAl*(2.0f*dxl0); g1 += gAl*(2.0f*dxl1); }
        if (hm) { g0 += gAu*(2.0f*dyu0); g1 += gAu*(2.0f*dyu1); }
        g0 = __fmul_rn(g0, 80.0f);
        g1 = __fmul_rn(g1, 80.0f);
        g0 = fminf(fmaxf(g0, -0.03f), 0.03f);
        g1 = fminf(fmaxf(g1, -0.03f), 0.03f);

        int e0 = base_b + pix, e1 = e0 + HW;
        dst[e0] = fminf(fmaxf(c0 - __fmul_rn(10.0f, g0), -1.0f), 1.0f);
        dst[e1] = fminf(fmaxf(c1 - __fmul_rn(10.0f, g1), -1.0f), 1.0f);
    }
}

// ---------------- energies: stage 1 (per-block partials) ----------------
__global__ void __launch_bounds__(256)
energy_partial(const float* __restrict__ buf, const float* __restrict__ target1,
               const float* __restrict__ input1, const float* __restrict__ input2)
{
    const int mode = blockIdx.z, b = blockIdx.y, blk = blockIdx.x;
    const int t = threadIdx.x;
    const int PPB = HW / EBLK;   // 2048
    float sd = 0.0f, ss = 0.0f;

    for (int i = t; i < PPB; i += 256) {
        int pix = blk*PPB + i;
        int h = pix / Ww, w = pix - h*Ww;

        // data term
        float A = 0.0f;
#pragma unroll
        for (int c = 0; c < 3; c++) {
            float i2    = input2[(b*3+c)*HW + pix];
            float img2p = ((i2*2.0f - 1.0f) + 1.0f) * 0.5f;
            float img1p;
            if (mode == 0) {
                float i1 = input1[(b*3+c)*HW + pix];
                img1p = ((i1*2.0f - 1.0f) + 1.0f) * 0.5f;
            } else {
                img1p = (buf[b*5*HW + (2+c)*HW + pix] + 1.0f) * 0.5f;
            }
            float d = img1p - img2p;
            A += d*d;
        }
        sd += sqrtf(A + 1e-5f);

        // smoothness term
        float Bx = 0.0f, By = 0.0f;
#pragma unroll
        for (int c = 0; c < 2; c++) {
            float f, fr = 0.0f, fd = 0.0f;
            if (mode == 0) {
                const float* tp = target1 + (b*2+c)*HW;
                f = (tp[pix] / 80.0f) * 80.0f;           // (target1/80)*80, fp-faithful
                if (w < Ww-1) fr = (tp[pix+1]  / 80.0f) * 80.0f;
                if (h < Hh-1) fd = (tp[pix+Ww] / 80.0f) * 80.0f;
            } else {
                const float* fp = buf + b*5*HW + c*HW;
                f = fp[pix] * 80.0f;
                if (w < Ww-1) fr = fp[pix+1]  * 80.0f;
                if (h < Hh-1) fd = fp[pix+Ww] * 80.0f;
            }
            if (w < Ww-1) { float dx = fr - f; Bx += dx*dx; }
            if (h < Hh-1) { float dy = fd - f; By += dy*dy; }
        }
        ss += sqrtf(Bx + By + 1e-5f);
    }

    __shared__ float rd[256], rs[256];
    rd[t] = sd; rs[t] = ss;
    __syncthreads();
    for (int s = 128; s > 0; s >>= 1) {
        if (t < s) { rd[t] += rd[t+s]; rs[t] += rs[t+s]; }
        __syncthreads();
    }
    if (t == 0) {
        int o = (mode*Bb + b)*EBLK + blk;
        g_part[2*o]   = rd[0];
        g_part[2*o+1] = rs[0];
    }
}

// ---------------- energies: stage 2 ----------------
__global__ void energy_final(const float* __restrict__ lw, float* __restrict__ out)
{
    int t = threadIdx.x;
    if (t >= 16) return;
    float sd = 0.0f, ss = 0.0f;
    for (int k = 0; k < EBLK; k++) {
        sd += g_part[2*(t*EBLK + k)];
        ss += g_part[2*(t*EBLK + k) + 1];
    }
    out[t] = (expf(lw[0])*sd + expf(lw[1])*ss) / 196608.0f;
}

// ---------------- output formatting ----------------
__global__ void __launch_bounds__(512)
format_kernel(const float* __restrict__ buf, float* __restrict__ out)
{
    int i = blockIdx.x*512 + threadIdx.x;
    if (i >= NFULL) return;
    int b = i / (5*HW);
    int r = i - b*5*HW;
    int c = r / HW;
    int pix = r - c*HW;
    if (c < 2)
        out[16 + (b*2 + c)*HW + pix] = buf[i] * 80.0f;
    else
        out[16 + Bb*2*HW + (b*3 + (c-2))*HW + pix] = (buf[i] + 1.0f) * 0.5f;
}

// ---------------- host threefry (for per-step keys) ----------------
static inline uint32_t h_rotl(uint32_t x, int d) { return (x << d) | (x >> (32 - d)); }
static void h_tf(uint32_t k0, uint32_t k1, uint32_t c0, uint32_t c1,
                 uint32_t& o0, uint32_t& o1)
{
    uint32_t ks2 = k0 ^ k1 ^ 0x1BD11BDAu;
    uint32_t x0 = c0 + k0, x1 = c1 + k1;
#define HR(r) { x0 += x1; x1 = h_rotl(x1, r); x1 ^= x0; }
    HR(13) HR(15) HR(26) HR(6)
    x0 += k1;  x1 += ks2 + 1u;
    HR(17) HR(29) HR(16) HR(24)
    x0 += ks2; x1 += k0 + 2u;
    HR(13) HR(15) HR(26) HR(6)
    x0 += k0;  x1 += k1 + 3u;
    HR(17) HR(29) HR(16) HR(24)
    x0 += k1;  x1 += ks2 + 4u;
    HR(13) HR(15) HR(26) HR(6)
    x0 += ks2; x1 += k0 + 5u;
#undef HR
    o0 = x0; o1 = x1;
}

extern "C" void kernel_launch(void* const* d_in, const int* in_sizes, int n_in,
                              void* d_out, int out_size)
{
    const float* target1 = (const float*)d_in[0];
    const float* input1  = (const float*)d_in[1];
    const float* input2  = (const float*)d_in[2];
    const float* init    = (const float*)d_in[3];
    const float* lw      = (const float*)d_in[4];
    float* out = (float*)d_out;

    float *pA, *pB;
    cudaGetSymbolAddress((void**)&pA, g_bufA);
    cudaGetSymbolAddress((void**)&pB, g_bufB);

    k_init<<<1, 1>>>(lw);

    dim3 grid(Ww/TW, Hh/TH, Bb);   // (16, 24, 8)
    const float* cur = init;
    for (int t = 0; t < NSTEPS; t++) {
        // keys[t] = threefry2x32(key=(0,1), counter=(0,t))  (foldlike split of key(1))
        uint32_t o0, o1;
        h_tf(0u, 1u, 0u, (uint32_t)t, o0, o1);
        float* dst = (t & 1) ? pB : pA;
        step_kernel<<<grid, TW*TH>>>(cur, dst, input2, o0, o1);
        cur = dst;
    }

    energy_partial<<<dim3(EBLK, Bb, 2), 256>>>(cur, target1, input1, input2);
    energy_final<<<1, 32>>>(lw, out);
    format_kernel<<<(NFULL + 511)/512, 512>>>(cur, out);
}

// round 9
// speedup vs baseline: 1.1601x; 1.1601x over previous
#include <cuda_runtime.h>
#include <cstdint>

#define Hh 384
#define Ww 512
#define Bb 8
#define HW (Hh*Ww)              // 196608
#define NFULL (Bb*5*HW)         // 7864320
#define NIMG  (Bb*3*HW)         // 4718592
#define NSTEPS 200
#define TW 32
#define TH 16
#define EBLK 96                 // partial blocks per (mode,batch): 196608/96 = 2048 px/block

// ---------------- static scratch (no allocation allowed) ----------------
__device__ float  g_bufA[NFULL];
__device__ float  g_bufB[NFULL];
__device__ float  g_img2p[NIMG];          // precomputed ((img2*2-1)+1)*0.5
__device__ float  g_K[2];
__device__ float  g_part[2*Bb*EBLK*2];

// ---------------- threefry2x32, JAX-exact, c0 = 0, N independent lanes ----
template<int N>
__device__ __forceinline__ void tf_bitsN(uint32_t k0, uint32_t k1,
                                         const uint32_t* c, uint32_t* r)
{
    const uint32_t ks2 = k0 ^ k1 ^ 0x1BD11BDAu;
    uint32_t x0[N], x1[N];
#pragma unroll
    for (int i = 0; i < N; i++) { x0[i] = k0; x1[i] = c[i] + k1; }

    auto rnd = [&](int rot) {
#pragma unroll
        for (int i = 0; i < N; i++) {
            x0[i] += x1[i];
            x1[i] = __funnelshift_l(x1[i], x1[i], rot);
            x1[i] ^= x0[i];
        }
    };
    auto inj = [&](uint32_t i0, uint32_t i1) {
#pragma unroll
        for (int i = 0; i < N; i++) { x0[i] += i0; x1[i] += i1; }
    };

    rnd(13); rnd(15); rnd(26); rnd(6);  inj(k1,  ks2 + 1u);
    rnd(17); rnd(29); rnd(16); rnd(24); inj(ks2, k0  + 2u);
    rnd(13); rnd(15); rnd(26); rnd(6);  inj(k0,  k1  + 3u);
    rnd(17); rnd(29); rnd(16); rnd(24); inj(k1,  ks2 + 4u);
    rnd(13); rnd(15); rnd(26); rnd(6);  inj(ks2, k0  + 5u);

#pragma unroll
    for (int i = 0; i < N; i++) r[i] = x0[i] ^ x1[i];
}

// ------------- jax.random.normal: uniform(lo,1) -> sqrt(2)*erfinv --------
// log1pf(-u*u) replaced by __logf(fma(-u,u,1)) — ~2ulp perturbation of w,
// well inside tolerance (dynamics are non-amplifying: clipped Langevin).
__device__ __forceinline__ float jax_normal(uint32_t bits)
{
    const float lo = __uint_as_float(0xBF7FFFFFu);      // nextafter(-1, 0)
    float f = __uint_as_float((bits >> 9) | 0x3F800000u) - 1.0f;  // [0,1)
    float u = fmaxf(lo, f * 2.0f + lo);                 // hi-lo rounds to 2.0f

    float w = -__logf(fmaf(-u, u, 1.0f));
    float p;
    if (w < 5.0f) {
        w = w - 2.5f;
        p =          2.81022636e-08f;
        p = p * w +  3.43273939e-07f;
        p = p * w + -3.5233877e-06f;
        p = p * w + -4.39150654e-06f;
        p = p * w +  0.00021858087f;
        p = p * w + -0.00125372503f;
        p = p * w + -0.00417768164f;
        p = p * w +  0.246640727f;
        p = p * w +  1.50140941f;
    } else {
        w = sqrtf(w) - 3.0f;
        p =         -0.000200214257f;
        p = p * w +  0.000100950558f;
        p = p * w +  0.00134934322f;
        p = p * w + -0.00367342844f;
        p = p * w +  0.00573950773f;
        p = p * w + -0.0076224613f;
        p = p * w +  0.00943887047f;
        p = p * w +  1.00167406f;
        p = p * w +  2.83297682f;
    }
    return 1.41421356237309515f * (p * u);
}

__device__ __forceinline__ float noised_clip(float x, float n)
{
    float d = __fmul_rn(0.05f, n);
    return fminf(fmaxf(x + d, -1.0f), 1.0f);
}

// ---------------- one-time prep: K and img2p ----------------
__global__ void k_init(const float* __restrict__ lw)
{
    g_K[0] = expf(lw[0]) / 196608.0f;
    g_K[1] = expf(lw[1]) / 196608.0f;
}

__global__ void __launch_bounds__(512)
prep_img2(const float* __restrict__ input2)
{
    int i = blockIdx.x*512 + threadIdx.x;
    if (i >= NIMG) return;
    float i2 = input2[i];
    g_img2p[i] = ((i2*2.0f - 1.0f) + 1.0f) * 0.5f;   // keep reference fp order
}

// ---------------- fused Langevin step: noise + analytic grad + update ----
__global__ void __launch_bounds__(TW*TH)
step_kernel(const float* __restrict__ src, float* __restrict__ dst,
            uint32_t k0, uint32_t k1)
{
    __shared__ float2 sft[TH+2][TW+2];     // noised+clipped flow (unscaled), 1-halo

    const int b  = blockIdx.z;
    const int h0 = blockIdx.y * TH;
    const int w0 = blockIdx.x * TW;
    const int tid = threadIdx.x;
    const int tx = tid & (TW-1), ty = tid / TW;
    const int base_b = b * 5 * HW;

    // fill flow tile + 1-halo: noised+clipped (halo noise recomputed; OOB -> 0, masked)
    for (int idx = tid; idx < (TH+2)*(TW+2); idx += TW*TH) {
        int hh = idx / (TW+2) - 1;
        int ww = idx - (hh+1)*(TW+2) - 1;
        int h = h0 + hh, w = w0 + ww;
        float y0 = 0.0f, y1 = 0.0f;
        if ((unsigned)h < (unsigned)Hh && (unsigned)w < (unsigned)Ww) {
            uint32_t ce[2];
            ce[0] = (uint32_t)(base_b + h*Ww + w);
            ce[1] = ce[0] + (uint32_t)HW;
            float xa = src[ce[0]], xb = src[ce[1]];
            uint32_t rb[2];
            tf_bitsN<2>(k0, k1, ce, rb);
            y0 = noised_clip(xa, jax_normal(rb[0]));
            y1 = noised_clip(xb, jax_normal(rb[1]));
        }
        sft[hh+1][ww+1] = make_float2(y0, y1);
    }
    __syncthreads();

    const int h = h0 + ty, w = w0 + tx;
    const int pix = h*Ww + w;
    const float K0 = g_K[0], K1 = g_K[1];

    // ---- image channels: local data-term gradient ----
    {
        uint32_t ce[3]; float xv[3], i2p[3];
#pragma unroll
        for (int c = 0; c < 3; c++) {
            ce[c]  = (uint32_t)(base_b + (2+c)*HW + pix);
            xv[c]  = src[ce[c]];
            i2p[c] = g_img2p[(b*3+c)*HW + pix];
        }
        uint32_t rb[3];
        tf_bitsN<3>(k0, k1, ce, rb);
        float yimg[3], diff[3], A = 0.0f;
#pragma unroll
        for (int c = 0; c < 3; c++) {
            float y = noised_clip(xv[c], jax_normal(rb[c]));
            yimg[c] = y;
            float img1p = (y + 1.0f) * 0.5f;
            float d = img1p - i2p[c];
            diff[c] = d;
            A += d*d;
        }
        float cD = K0 * (0.5f / sqrtf(A + 1e-5f));
#pragma unroll
        for (int c = 0; c < 3; c++) {
            float g = cD * diff[c];
            g = fminf(fmaxf(g, -0.03f), 0.03f);
            float sg = __fmul_rn(10.0f, g);
            dst[ce[c]] = fminf(fmaxf(yimg[c] - sg, -1.0f), 1.0f);
        }
    }

    // ---- flow channels: smoothness-term stencil gradient ----
    {
        const int si = ty + 1, sj = tx + 1;
        const bool wp = (w < Ww-1), hp = (h < Hh-1);
        const bool wm = (w > 0),    hm = (h > 0);

        float2 tc  = sft[si][sj];
        float2 tr  = sft[si][sj+1];
        float2 td  = sft[si+1][sj];
        float2 tl  = sft[si][sj-1];
        float2 tu  = sft[si-1][sj];
        float2 tdl = sft[si+1][sj-1];
        float2 tur = sft[si-1][sj+1];

        float f0  = tc.x*80.0f,  f1  = tc.y*80.0f;
        float f0r = tr.x*80.0f,  f1r = tr.y*80.0f;
        float f0d = td.x*80.0f,  f1d = td.y*80.0f;
        float f0l = tl.x*80.0f,  f1l = tl.y*80.0f;
        float f0u = tu.x*80.0f,  f1u = tu.y*80.0f;
        float f0dl= tdl.x*80.0f, f1dl= tdl.y*80.0f;
        float f0ur= tur.x*80.0f, f1ur= tur.y*80.0f;

        // R at (h, w)
        float dx0 = f0r - f0, dx1 = f1r - f1;
        float dy0 = f0d - f0, dy1 = f1d - f1;
        float Sc = (wp ? dx0*dx0 + dx1*dx1 : 0.0f)
                 + (hp ? dy0*dy0 + dy1*dy1 : 0.0f) + 1e-5f;
        float gAc = K1 * (0.5f / sqrtf(Sc));

        // R at (h, w-1): Bx valid iff wm; By valid iff hp
        float dxl0 = f0 - f0l,   dxl1 = f1 - f1l;
        float dyl0 = f0dl - f0l, dyl1 = f1dl - f1l;
        float Sl = (dxl0*dxl0 + dxl1*dxl1)
                 + (hp ? dyl0*dyl0 + dyl1*dyl1 : 0.0f) + 1e-5f;
        float gAl = K1 * (0.5f / sqrtf(Sl));

        // R at (h-1, w): By valid iff hm; Bx valid iff wp
        float dxu0 = f0ur - f0u, dxu1 = f1ur - f1u;
        float dyu0 = f0 - f0u,   dyu1 = f1 - f1u;
        float Su = (wp ? dxu0*dxu0 + dxu1*dxu1 : 0.0f)
                 + (dyu0*dyu0 + dyu1*dyu1) + 1e-5f;
        float gAu = K1 * (0.5f / sqrtf(Su));

        float g0 = 0.0f, g1 = 0.0f;
        if (wp) { g0 -= gAc*(2.0f*dx0);  g1 -= gAc*(2.0f*dx1);  }
        if (hp) { g0 -= gAc*(2.0f*dy0);  g1 -= gAc*(2.0f*dy1);  }
        if (wm) { g0 += gAl*(2.0f*dxl0); g1 += gAl*(2.0f*dxl1); }
        if (hm) { g0 += gAu*(2.0f*dyu0); g1 += gAu*(2.0f*dyu1); }
        g0 = __fmul_rn(g0, 80.0f);
        g1 = __fmul_rn(g1, 80.0f);
        g0 = fminf(fmaxf(g0, -0.03f), 0.03f);
        g1 = fminf(fmaxf(g1, -0.03f), 0.03f);

        int e0 = base_b + pix, e1 = e0 + HW;
        dst[e0] = fminf(fmaxf(tc.x - __fmul_rn(10.0f, g0), -1.0f), 1.0f);
        dst[e1] = fminf(fmaxf(tc.y - __fmul_rn(10.0f, g1), -1.0f), 1.0f);
    }
}

// ---------------- energies: stage 1 (per-block partials) ----------------
__global__ void __launch_bounds__(256)
energy_partial(const float* __restrict__ buf, const float* __restrict__ target1,
               const float* __restrict__ input1)
{
    const int mode = blockIdx.z, b = blockIdx.y, blk = blockIdx.x;
    const int t = threadIdx.x;
    const int PPB = HW / EBLK;   // 2048
    float sd = 0.0f, ss = 0.0f;

    for (int i = t; i < PPB; i += 256) {
        int pix = blk*PPB + i;
        int h = pix / Ww, w = pix - h*Ww;

        // data term
        float A = 0.0f;
#pragma unroll
        for (int c = 0; c < 3; c++) {
            float img2p = g_img2p[(b*3+c)*HW + pix];
            float img1p;
            if (mode == 0) {
                float i1 = input1[(b*3+c)*HW + pix];
                img1p = ((i1*2.0f - 1.0f) + 1.0f) * 0.5f;
            } else {
                img1p = (buf[b*5*HW + (2+c)*HW + pix] + 1.0f) * 0.5f;
            }
            float d = img1p - img2p;
            A += d*d;
        }
        sd += sqrtf(A + 1e-5f);

        // smoothness term
        float Bx = 0.0f, By = 0.0f;
#pragma unroll
        for (int c = 0; c < 2; c++) {
            float f, fr = 0.0f, fd = 0.0f;
            if (mode == 0) {
                const float* tp = target1 + (b*2+c)*HW;
                f = (tp[pix] / 80.0f) * 80.0f;           // (target1/80)*80, fp-faithful
                if (w < Ww-1) fr = (tp[pix+1]  / 80.0f) * 80.0f;
                if (h < Hh-1) fd = (tp[pix+Ww] / 80.0f) * 80.0f;
            } else {
                const float* fp = buf + b*5*HW + c*HW;
                f = fp[pix] * 80.0f;
                if (w < Ww-1) fr = fp[pix+1]  * 80.0f;
                if (h < Hh-1) fd = fp[pix+Ww] * 80.0f;
            }
            if (w < Ww-1) { float dx = fr - f; Bx += dx*dx; }
            if (h < Hh-1) { float dy = fd - f; By += dy*dy; }
        }
        ss += sqrtf(Bx + By + 1e-5f);
    }

    __shared__ float rd[256], rs[256];
    rd[t] = sd; rs[t] = ss;
    __syncthreads();
    for (int s = 128; s > 0; s >>= 1) {
        if (t < s) { rd[t] += rd[t+s]; rs[t] += rs[t+s]; }
        __syncthreads();
    }
    if (t == 0) {
        int o = (mode*Bb + b)*EBLK + blk;
        g_part[2*o]   = rd[0];
        g_part[2*o+1] = rs[0];
    }
}

// ---------------- energies: stage 2 ----------------
__global__ void energy_final(const float* __restrict__ lw, float* __restrict__ out)
{
    int t = threadIdx.x;
    if (t >= 16) return;
    float sd = 0.0f, ss = 0.0f;
    for (int k = 0; k < EBLK; k++) {
        sd += g_part[2*(t*EBLK + k)];
        ss += g_part[2*(t*EBLK + k) + 1];
    }
    out[t] = (expf(lw[0])*sd + expf(lw[1])*ss) / 196608.0f;
}

// ---------------- output formatting ----------------
__global__ void __launch_bounds__(512)
format_kernel(const float* __restrict__ buf, float* __restrict__ out)
{
    int i = blockIdx.x*512 + threadIdx.x;
    if (i >= NFULL) return;
    int b = i / (5*HW);
    int r = i - b*5*HW;
    int c = r / HW;
    int pix = r - c*HW;
    if (c < 2)
        out[16 + (b*2 + c)*HW + pix] = buf[i] * 80.0f;
    else
        out[16 + Bb*2*HW + (b*3 + (c-2))*HW + pix] = (buf[i] + 1.0f) * 0.5f;
}

// ---------------- host threefry (for per-step keys) ----------------
static inline uint32_t h_rotl(uint32_t x, int d) { return (x << d) | (x >> (32 - d)); }
static void h_tf(uint32_t k0, uint32_t k1, uint32_t c0, uint32_t c1,
                 uint32_t& o0, uint32_t& o1)
{
    uint32_t ks2 = k0 ^ k1 ^ 0x1BD11BDAu;
    uint32_t x0 = c0 + k0, x1 = c1 + k1;
#define HR(r) { x0 += x1; x1 = h_rotl(x1, r); x1 ^= x0; }
    HR(13) HR(15) HR(26) HR(6)
    x0 += k1;  x1 += ks2 + 1u;
    HR(17) HR(29) HR(16) HR(24)
    x0 += ks2; x1 += k0 + 2u;
    HR(13) HR(15) HR(26) HR(6)
    x0 += k0;  x1 += k1 + 3u;
    HR(17) HR(29) HR(16) HR(24)
    x0 += k1;  x1 += ks2 + 4u;
    HR(13) HR(15) HR(26) HR(6)
    x0 += ks2; x1 += k0 + 5u;
#undef HR
    o0 = x0; o1 = x1;
}

extern "C" void kernel_launch(void* const* d_in, const int* in_sizes, int n_in,
                              void* d_out, int out_size)
{
    const float* target1 = (const float*)d_in[0];
    const float* input1  = (const float*)d_in[1];
    const float* input2  = (const float*)d_in[2];
    const float* init    = (const float*)d_in[3];
    const float* lw      = (const float*)d_in[4];
    float* out = (float*)d_out;

    float *pA, *pB;
    cudaGetSymbolAddress((void**)&pA, g_bufA);
    cudaGetSymbolAddress((void**)&pB, g_bufB);

    k_init<<<1, 1>>>(lw);
    prep_img2<<<(NIMG + 511)/512, 512>>>(input2);

    dim3 grid(Ww/TW, Hh/TH, Bb);   // (16, 24, 8)
    const float* cur = init;
    for (int t = 0; t < NSTEPS; t++) {
        // keys[t] = threefry2x32(key=(0,1), counter=(0,t))  (foldlike split of key(1))
        uint32_t o0, o1;
        h_tf(0u, 1u, 0u, (uint32_t)t, o0, o1);
        float* dst = (t & 1) ? pB : pA;
        step_kernel<<<grid, TW*TH>>>(cur, dst, o0, o1);
        cur = dst;
    }

    energy_partial<<<dim3(EBLK, Bb, 2), 256>>>(cur, target1, input1);
    energy_final<<<1, 32>>>(lw, out);
    format_kernel<<<(NFULL + 511)/512, 512>>>(cur, out);
}

// round 10
// speedup vs baseline: 1.2771x; 1.1008x over previous
#include <cuda_runtime.h>
#include <cstdint>

#define Hh 384
#define Ww 512
#define Bb 8
#define HW (Hh*Ww)              // 196608
#define NFULL (Bb*5*HW)         // 7864320
#define NIMG  (Bb*3*HW)         // 4718592
#define NSTEPS 200
#define TW 32
#define TH 16
#define EBLK 96                 // partial blocks per (mode,batch): 196608/96 = 2048 px/block

// ---------------- static scratch (no allocation allowed) ----------------
__device__ float  g_bufA[NFULL];
__device__ float  g_bufB[NFULL];
__device__ float  g_img2p[NIMG];          // precomputed ((img2*2-1)+1)*0.5
__device__ float  g_K[2];
__device__ float  g_part[2*Bb*EBLK*2];

// ---------------- threefry2x32, JAX-exact, c0 = 0, N independent lanes ----
template<int N>
__device__ __forceinline__ void tf_bitsN(uint32_t k0, uint32_t k1,
                                         const uint32_t* c, uint32_t* r)
{
    const uint32_t ks2 = k0 ^ k1 ^ 0x1BD11BDAu;
    uint32_t x0[N], x1[N];
#pragma unroll
    for (int i = 0; i < N; i++) { x0[i] = k0; x1[i] = c[i] + k1; }

    auto rnd = [&](int rot) {
#pragma unroll
        for (int i = 0; i < N; i++) {
            x0[i] += x1[i];
            x1[i] = __funnelshift_l(x1[i], x1[i], rot);
            x1[i] ^= x0[i];
        }
    };
    auto inj = [&](uint32_t i0, uint32_t i1) {
#pragma unroll
        for (int i = 0; i < N; i++) { x0[i] += i0; x1[i] += i1; }
    };

    rnd(13); rnd(15); rnd(26); rnd(6);  inj(k1,  ks2 + 1u);
    rnd(17); rnd(29); rnd(16); rnd(24); inj(ks2, k0  + 2u);
    rnd(13); rnd(15); rnd(26); rnd(6);  inj(k0,  k1  + 3u);
    rnd(17); rnd(29); rnd(16); rnd(24); inj(k1,  ks2 + 4u);
    rnd(13); rnd(15); rnd(26); rnd(6);  inj(ks2, k0  + 5u);

#pragma unroll
    for (int i = 0; i < N; i++) r[i] = x0[i] ^ x1[i];
}

// ------------- jax.random.normal: uniform(lo,1) -> sqrt(2)*erfinv --------
__device__ __forceinline__ float jax_normal(uint32_t bits)
{
    const float lo = __uint_as_float(0xBF7FFFFFu);      // nextafter(-1, 0)
    float f = __uint_as_float((bits >> 9) | 0x3F800000u) - 1.0f;  // [0,1)
    float u = fmaxf(lo, f * 2.0f + lo);                 // hi-lo rounds to 2.0f

    float w = -__logf(fmaf(-u, u, 1.0f));
    float p;
    if (w < 5.0f) {
        w = w - 2.5f;
        p =          2.81022636e-08f;
        p = p * w +  3.43273939e-07f;
        p = p * w + -3.5233877e-06f;
        p = p * w + -4.39150654e-06f;
        p = p * w +  0.00021858087f;
        p = p * w + -0.00125372503f;
        p = p * w + -0.00417768164f;
        p = p * w +  0.246640727f;
        p = p * w +  1.50140941f;
    } else {
        w = sqrtf(w) - 3.0f;
        p =         -0.000200214257f;
        p = p * w +  0.000100950558f;
        p = p * w +  0.00134934322f;
        p = p * w + -0.00367342844f;
        p = p * w +  0.00573950773f;
        p = p * w + -0.0076224613f;
        p = p * w +  0.00943887047f;
        p = p * w +  1.00167406f;
        p = p * w +  2.83297682f;
    }
    return 1.41421356237309515f * (p * u);
}

__device__ __forceinline__ float noised_clip(float x, float n)
{
    float d = __fmul_rn(0.05f, n);
    return fminf(fmaxf(x + d, -1.0f), 1.0f);
}

// ---------------- one-time prep: K and img2p ----------------
__global__ void k_init(const float* __restrict__ lw)
{
    g_K[0] = expf(lw[0]) / 196608.0f;
    g_K[1] = expf(lw[1]) / 196608.0f;
}

__global__ void __launch_bounds__(512)
prep_img2(const float* __restrict__ input2)
{
    int i = blockIdx.x*512 + threadIdx.x;
    if (i >= NIMG) return;
    float i2 = input2[i];
    g_img2p[i] = ((i2*2.0f - 1.0f) + 1.0f) * 0.5f;   // keep reference fp order
}

// ---------------- fused Langevin step: noise + analytic grad + update ----
// Interior: one tf_bitsN<5> per thread (ILP 5). Halo ring: exactly 100 cells,
// threads 0..99 each do one tf_bitsN<2>.
__global__ void __launch_bounds__(TW*TH)
step_kernel(const float* __restrict__ src, float* __restrict__ dst,
            uint32_t k0, uint32_t k1)
{
    __shared__ float2 sft[TH+2][TW+2];     // noised+clipped flow (unscaled), 1-halo

    const int b  = blockIdx.z;
    const int h0 = blockIdx.y * TH;
    const int w0 = blockIdx.x * TW;
    const int tid = threadIdx.x;
    const int tx = tid & (TW-1), ty = tid >> 5;
    const int base_b = b * 5 * HW;

    const int h = h0 + ty, w = w0 + tx;
    const int pix = h*Ww + w;

    // ---- interior: 5 counters (2 flow + 3 img), front-batched loads ----
    uint32_t ce[5];
    ce[0] = (uint32_t)(base_b + pix);
    ce[1] = ce[0] + (uint32_t)HW;
    ce[2] = ce[0] + (uint32_t)(2*HW);
    ce[3] = ce[0] + (uint32_t)(3*HW);
    ce[4] = ce[0] + (uint32_t)(4*HW);

    float xv[5], i2p[3];
#pragma unroll
    for (int i = 0; i < 5; i++) xv[i] = src[ce[i]];
#pragma unroll
    for (int c = 0; c < 3; c++) i2p[c] = g_img2p[(b*3+c)*HW + pix];

    uint32_t rb[5];
    tf_bitsN<5>(k0, k1, ce, rb);

    float y0 = noised_clip(xv[0], jax_normal(rb[0]));
    float y1 = noised_clip(xv[1], jax_normal(rb[1]));
    sft[ty+1][tx+1] = make_float2(y0, y1);

    // ---- halo ring: 100 = (TH+2)*(TW+2) - TH*TW cells ----
    if (tid < 2*(TW+2) + 2*TH) {           // 100
        int hh, ww;
        if (tid < (TW+2))            { hh = -1; ww = tid - 1; }
        else if (tid < 2*(TW+2))     { hh = TH; ww = tid - (TW+2) - 1; }
        else if (tid < 2*(TW+2)+TH)  { hh = tid - 2*(TW+2); ww = -1; }
        else                         { hh = tid - (2*(TW+2)+TH); ww = TW; }
        int hg = h0 + hh, wg = w0 + ww;
        float z0 = 0.0f, z1 = 0.0f;
        if ((unsigned)hg < (unsigned)Hh && (unsigned)wg < (unsigned)Ww) {
            uint32_t he[2];
            he[0] = (uint32_t)(base_b + hg*Ww + wg);
            he[1] = he[0] + (uint32_t)HW;
            float xa = src[he[0]], xb = src[he[1]];
            uint32_t hb[2];
            tf_bitsN<2>(k0, k1, he, hb);
            z0 = noised_clip(xa, jax_normal(hb[0]));
            z1 = noised_clip(xb, jax_normal(hb[1]));
        }
        sft[hh+1][ww+1] = make_float2(z0, z1);
    }
    __syncthreads();

    const float K0 = g_K[0], K1 = g_K[1];

    // ---- image channels: local data-term gradient ----
    {
        float yimg[3], diff[3], A = 0.0f;
#pragma unroll
        for (int c = 0; c < 3; c++) {
            float y = noised_clip(xv[2+c], jax_normal(rb[2+c]));
            yimg[c] = y;
            float img1p = (y + 1.0f) * 0.5f;
            float d = img1p - i2p[c];
            diff[c] = d;
            A += d*d;
        }
        float cD = K0 * (0.5f / sqrtf(A + 1e-5f));
#pragma unroll
        for (int c = 0; c < 3; c++) {
            float g = cD * diff[c];
            g = fminf(fmaxf(g, -0.03f), 0.03f);
            float sg = __fmul_rn(10.0f, g);
            dst[ce[2+c]] = fminf(fmaxf(yimg[c] - sg, -1.0f), 1.0f);
        }
    }

    // ---- flow channels: smoothness-term stencil gradient ----
    {
        const int si = ty + 1, sj = tx + 1;
        const bool wp = (w < Ww-1), hp = (h < Hh-1);
        const bool wm = (w > 0),    hm = (h > 0);

        float2 tc  = sft[si][sj];
        float2 tr  = sft[si][sj+1];
        float2 td  = sft[si+1][sj];
        float2 tl  = sft[si][sj-1];
        float2 tu  = sft[si-1][sj];
        float2 tdl = sft[si+1][sj-1];
        float2 tur = sft[si-1][sj+1];

        float f0  = tc.x*80.0f,  f1  = tc.y*80.0f;
        float f0r = tr.x*80.0f,  f1r = tr.y*80.0f;
        float f0d = td.x*80.0f,  f1d = td.y*80.0f;
        float f0l = tl.x*80.0f,  f1l = tl.y*80.0f;
        float f0u = tu.x*80.0f,  f1u = tu.y*80.0f;
        float f0dl= tdl.x*80.0f, f1dl= tdl.y*80.0f;
        float f0ur= tur.x*80.0f, f1ur= tur.y*80.0f;

        // R at (h, w)
        float dx0 = f0r - f0, dx1 = f1r - f1;
        float dy0 = f0d - f0, dy1 = f1d - f1;
        float Sc = (wp ? dx0*dx0 + dx1*dx1 : 0.0f)
                 + (hp ? dy0*dy0 + dy1*dy1 : 0.0f) + 1e-5f;
        float gAc = K1 * (0.5f / sqrtf(Sc));

        // R at (h, w-1): Bx valid iff wm; By valid iff hp
        float dxl0 = f0 - f0l,   dxl1 = f1 - f1l;
        float dyl0 = f0dl - f0l, dyl1 = f1dl - f1l;
        float Sl = (dxl0*dxl0 + dxl1*dxl1)
                 + (hp ? dyl0*dyl0 + dyl1*dyl1 : 0.0f) + 1e-5f;
        float gAl = K1 * (0.5f / sqrtf(Sl));

        // R at (h-1, w): By valid iff hm; Bx valid iff wp
        float dxu0 = f0ur - f0u, dxu1 = f1ur - f1u;
        float dyu0 = f0 - f0u,   dyu1 = f1 - f1u;
        float Su = (wp ? dxu0*dxu0 + dxu1*dxu1 : 0.0f)
                 + (dyu0*dyu0 + dyu1*dyu1) + 1e-5f;
        float gAu = K1 * (0.5f / sqrtf(Su));

        float g0 = 0.0f, g1 = 0.0f;
        if (wp) { g0 -= gAc*(2.0f*dx0);  g1 -= gAc*(2.0f*dx1);  }
        if (hp) { g0 -= gAc*(2.0f*dy0);  g1 -= gAc*(2.0f*dy1);  }
        if (wm) { g0 += gAl*(2.0f*dxl0); g1 += gAl*(2.0f*dxl1); }
        if (hm) { g0 += gAu*(2.0f*dyu0); g1 += gAu*(2.0f*dyu1); }
        g0 = __fmul_rn(g0, 80.0f);
        g1 = __fmul_rn(g1, 80.0f);
        g0 = fminf(fmaxf(g0, -0.03f), 0.03f);
        g1 = fminf(fmaxf(g1, -0.03f), 0.03f);

        dst[ce[0]] = fminf(fmaxf(tc.x - __fmul_rn(10.0f, g0), -1.0f), 1.0f);
        dst[ce[1]] = fminf(fmaxf(tc.y - __fmul_rn(10.0f, g1), -1.0f), 1.0f);
    }
}

// ---------------- energies: stage 1 (per-block partials) ----------------
__global__ void __launch_bounds__(256)
energy_partial(const float* __restrict__ buf, const float* __restrict__ target1,
               const float* __restrict__ input1)
{
    const int mode = blockIdx.z, b = blockIdx.y, blk = blockIdx.x;
    const int t = threadIdx.x;
    const int PPB = HW / EBLK;   // 2048
    float sd = 0.0f, ss = 0.0f;

    for (int i = t; i < PPB; i += 256) {
        int pix = blk*PPB + i;
        int h = pix / Ww, w = pix - h*Ww;

        // data term
        float A = 0.0f;
#pragma unroll
        for (int c = 0; c < 3; c++) {
            float img2p = g_img2p[(b*3+c)*HW + pix];
            float img1p;
            if (mode == 0) {
                float i1 = input1[(b*3+c)*HW + pix];
                img1p = ((i1*2.0f - 1.0f) + 1.0f) * 0.5f;
            } else {
                img1p = (buf[b*5*HW + (2+c)*HW + pix] + 1.0f) * 0.5f;
            }
            float d = img1p - img2p;
            A += d*d;
        }
        sd += sqrtf(A + 1e-5f);

        // smoothness term
        float Bx = 0.0f, By = 0.0f;
#pragma unroll
        for (int c = 0; c < 2; c++) {
            float f, fr = 0.0f, fd = 0.0f;
            if (mode == 0) {
                const float* tp = target1 + (b*2+c)*HW;
                f = (tp[pix] / 80.0f) * 80.0f;           // (target1/80)*80, fp-faithful
                if (w < Ww-1) fr = (tp[pix+1]  / 80.0f) * 80.0f;
                if (h < Hh-1) fd = (tp[pix+Ww] / 80.0f) * 80.0f;
            } else {
                const float* fp = buf + b*5*HW + c*HW;
                f = fp[pix] * 80.0f;
                if (w < Ww-1) fr = fp[pix+1]  * 80.0f;
                if (h < Hh-1) fd = fp[pix+Ww] * 80.0f;
            }
            if (w < Ww-1) { float dx = fr - f; Bx += dx*dx; }
            if (h < Hh-1) { float dy = fd - f; By += dy*dy; }
        }
        ss += sqrtf(Bx + By + 1e-5f);
    }

    __shared__ float rd[256], rs[256];
    rd[t] = sd; rs[t] = ss;
    __syncthreads();
    for (int s = 128; s > 0; s >>= 1) {
        if (t < s) { rd[t] += rd[t+s]; rs[t] += rs[t+s]; }
        __syncthreads();
    }
    if (t == 0) {
        int o = (mode*Bb + b)*EBLK + blk;
        g_part[2*o]   = rd[0];
        g_part[2*o+1] = rs[0];
    }
}

// ---------------- energies: stage 2 ----------------
__global__ void energy_final(const float* __restrict__ lw, float* __restrict__ out)
{
    int t = threadIdx.x;
    if (t >= 16) return;
    float sd = 0.0f, ss = 0.0f;
    for (int k = 0; k < EBLK; k++) {
        sd += g_part[2*(t*EBLK + k)];
        ss += g_part[2*(t*EBLK + k) + 1];
    }
    out[t] = (expf(lw[0])*sd + expf(lw[1])*ss) / 196608.0f;
}

// ---------------- output formatting ----------------
__global__ void __launch_bounds__(512)
format_kernel(const float* __restrict__ buf, float* __restrict__ out)
{
    int i = blockIdx.x*512 + threadIdx.x;
    if (i >= NFULL) return;
    int b = i / (5*HW);
    int r = i - b*5*HW;
    int c = r / HW;
    int pix = r - c*HW;
    if (c < 2)
        out[16 + (b*2 + c)*HW + pix] = buf[i] * 80.0f;
    else
        out[16 + Bb*2*HW + (b*3 + (c-2))*HW + pix] = (buf[i] + 1.0f) * 0.5f;
}

// ---------------- host threefry (for per-step keys) ----------------
static inline uint32_t h_rotl(uint32_t x, int d) { return (x << d) | (x >> (32 - d)); }
static void h_tf(uint32_t k0, uint32_t k1, uint32_t c0, uint32_t c1,
                 uint32_t& o0, uint32_t& o1)
{
    uint32_t ks2 = k0 ^ k1 ^ 0x1BD11BDAu;
    uint32_t x0 = c0 + k0, x1 = c1 + k1;
#define HR(r) { x0 += x1; x1 = h_rotl(x1, r); x1 ^= x0; }
    HR(13) HR(15) HR(26) HR(6)
    x0 += k1;  x1 += ks2 + 1u;
    HR(17) HR(29) HR(16) HR(24)
    x0 += ks2; x1 += k0 + 2u;
    HR(13) HR(15) HR(26) HR(6)
    x0 += k0;  x1 += k1 + 3u;
    HR(17) HR(29) HR(16) HR(24)
    x0 += k1;  x1 += ks2 + 4u;
    HR(13) HR(15) HR(26) HR(6)
    x0 += ks2; x1 += k0 + 5u;
#undef HR
    o0 = x0; o1 = x1;
}

extern "C" void kernel_launch(void* const* d_in, const int* in_sizes, int n_in,
                              void* d_out, int out_size)
{
    const float* target1 = (const float*)d_in[0];
    const float* input1  = (const float*)d_in[1];
    const float* input2  = (const float*)d_in[2];
    const float* init    = (const float*)d_in[3];
    const float* lw      = (const float*)d_in[4];
    float* out = (float*)d_out;

    float *pA, *pB;
    cudaGetSymbolAddress((void**)&pA, g_bufA);
    cudaGetSymbolAddress((void**)&pB, g_bufB);

    k_init<<<1, 1>>>(lw);
    prep_img2<<<(NIMG + 511)/512, 512>>>(input2);

    dim3 grid(Ww/TW, Hh/TH, Bb);   // (16, 24, 8)
    const float* cur = init;
    for (int t = 0; t < NSTEPS; t++) {
        // keys[t] = threefry2x32(key=(0,1), counter=(0,t))  (foldlike split of key(1))
        uint32_t o0, o1;
        h_tf(0u, 1u, 0u, (uint32_t)t, o0, o1);
        float* dst = (t & 1) ? pB : pA;
        step_kernel<<<grid, TW*TH>>>(cur, dst, o0, o1);
        cur = dst;
    }

    energy_partial<<<dim3(EBLK, Bb, 2), 256>>>(cur, target1, input1);
    energy_final<<<1, 32>>>(lw, out);
    format_kernel<<<(NFULL + 511)/512, 512>>>(cur, out);
}

// round 11
// speedup vs baseline: 1.3283x; 1.0402x over previous
#include <cuda_runtime.h>
#include <cstdint>

#define Hh 384
#define Ww 512
#define Bb 8
#define HW (Hh*Ww)              // 196608
#define NFULL (Bb*5*HW)         // 7864320
#define NIMG  (Bb*3*HW)         // 4718592
#define NSTEPS 200
#define TW 32
#define TH 16
#define EBLK 96

// ---------------- static scratch (no allocation allowed) ----------------
// AoS scratch: 8 floats per (b,pix); channels 0..4 used (2 flow + 3 img).
__device__ float  g_bufA[Bb*HW*8];
__device__ float  g_bufB[Bb*HW*8];
// img2p AoS: 4 floats per (b,pix); channels 0..2 used.
__device__ float  g_img2p[Bb*HW*4];
__device__ float  g_K[2];
__device__ float  g_part[2*Bb*EBLK*2];

// ---------------- threefry2x32, JAX-exact, c0 = 0, N independent lanes ----
template<int N>
__device__ __forceinline__ void tf_bitsN(uint32_t k0, uint32_t k1,
                                         const uint32_t* c, uint32_t* r)
{
    const uint32_t ks2 = k0 ^ k1 ^ 0x1BD11BDAu;
    uint32_t x0[N], x1[N];
#pragma unroll
    for (int i = 0; i < N; i++) { x0[i] = k0; x1[i] = c[i] + k1; }

    auto rnd = [&](int rot) {
#pragma unroll
        for (int i = 0; i < N; i++) {
            x0[i] += x1[i];
            x1[i] = __funnelshift_l(x1[i], x1[i], rot);
            x1[i] ^= x0[i];
        }
    };
    auto inj = [&](uint32_t i0, uint32_t i1) {
#pragma unroll
        for (int i = 0; i < N; i++) { x0[i] += i0; x1[i] += i1; }
    };

    rnd(13); rnd(15); rnd(26); rnd(6);  inj(k1,  ks2 + 1u);
    rnd(17); rnd(29); rnd(16); rnd(24); inj(ks2, k0  + 2u);
    rnd(13); rnd(15); rnd(26); rnd(6);  inj(k0,  k1  + 3u);
    rnd(17); rnd(29); rnd(16); rnd(24); inj(k1,  ks2 + 4u);
    rnd(13); rnd(15); rnd(26); rnd(6);  inj(ks2, k0  + 5u);

#pragma unroll
    for (int i = 0; i < N; i++) r[i] = x0[i] ^ x1[i];
}

// ------------- jax.random.normal: uniform(lo,1) -> sqrt(2)*erfinv --------
__device__ __forceinline__ float jax_normal(uint32_t bits)
{
    const float lo = __uint_as_float(0xBF7FFFFFu);      // nextafter(-1, 0)
    float f = __uint_as_float((bits >> 9) | 0x3F800000u) - 1.0f;  // [0,1)
    float u = fmaxf(lo, f * 2.0f + lo);

    float w = -__logf(fmaf(-u, u, 1.0f));
    float p;
    if (w < 5.0f) {
        w = w - 2.5f;
        p =          2.81022636e-08f;
        p = p * w +  3.43273939e-07f;
        p = p * w + -3.5233877e-06f;
        p = p * w + -4.39150654e-06f;
        p = p * w +  0.00021858087f;
        p = p * w + -0.00125372503f;
        p = p * w + -0.00417768164f;
        p = p * w +  0.246640727f;
        p = p * w +  1.50140941f;
    } else {
        w = sqrtf(w) - 3.0f;
        p =         -0.000200214257f;
        p = p * w +  0.000100950558f;
        p = p * w +  0.00134934322f;
        p = p * w + -0.00367342844f;
        p = p * w +  0.00573950773f;
        p = p * w + -0.0076224613f;
        p = p * w +  0.00943887047f;
        p = p * w +  1.00167406f;
        p = p * w +  2.83297682f;
    }
    return 1.41421356237309515f * (p * u);
}

// x + 0.05*n, clipped (FMA-fused; <=1ulp vs reference per step, non-amplifying)
__device__ __forceinline__ float noised_clip(float x, float n)
{
    return fminf(fmaxf(fmaf(0.05f, n, x), -1.0f), 1.0f);
}

// ---------------- one-time prep: K and img2p ----------------
__global__ void k_init(const float* __restrict__ lw)
{
    g_K[0] = expf(lw[0]) / 196608.0f;
    g_K[1] = expf(lw[1]) / 196608.0f;
}

__global__ void __launch_bounds__(512)
prep_img2(const float* __restrict__ input2)
{
    int i = blockIdx.x*512 + threadIdx.x;
    if (i >= NIMG) return;
    int b   = i / (3*HW);
    int r   = i - b*3*HW;
    int c   = r / HW;
    int pix = r - c*HW;
    float i2 = input2[i];
    g_img2p[(b*HW + pix)*4 + c] = ((i2*2.0f - 1.0f) + 1.0f) * 0.5f;
}

// ---------------- fused Langevin step: noise + analytic grad + update ----
template<bool SRC_PLANAR>
__global__ void __launch_bounds__(TW*TH, 3)
step_kernel(const float* __restrict__ src, float* __restrict__ dst,
            uint32_t k0, uint32_t k1)
{
    __shared__ float2 sft[TH+2][TW+2];     // SCALED (x80) noised flow, 1-halo

    const int b  = blockIdx.z;
    const int h0 = blockIdx.y * TH;
    const int w0 = blockIdx.x * TW;
    const int tid = threadIdx.x;
    const int tx = tid & (TW-1), ty = tid >> 5;
    const int base_b = b * 5 * HW;

    const int h = h0 + ty, w = w0 + tx;
    const int pix  = h*Ww + w;
    const int bpix = b*HW + pix;

    // ---- counters = JAX planar flat indices ----
    uint32_t ce[5];
    ce[0] = (uint32_t)(base_b + pix);
#pragma unroll
    for (int i = 1; i < 5; i++) ce[i] = ce[0] + (uint32_t)(i*HW);

    // ---- front-batched loads ----
    float xv[5];
    if (SRC_PLANAR) {
#pragma unroll
        for (int i = 0; i < 5; i++) xv[i] = src[ce[i]];
    } else {
        float4 v4 = *reinterpret_cast<const float4*>(src + (size_t)bpix*8);
        xv[0] = v4.x; xv[1] = v4.y; xv[2] = v4.z; xv[3] = v4.w;
        xv[4] = src[(size_t)bpix*8 + 4];
    }
    float4 i2p4 = *reinterpret_cast<const float4*>(g_img2p + (size_t)bpix*4);

    uint32_t rb[5];
    tf_bitsN<5>(k0, k1, ce, rb);

    float y0 = noised_clip(xv[0], jax_normal(rb[0]));
    float y1 = noised_clip(xv[1], jax_normal(rb[1]));
    float f0 = y0*80.0f, f1 = y1*80.0f;
    sft[ty+1][tx+1] = make_float2(f0, f1);

    // ---- halo ring: 100 cells, threads 0..99 ----
    if (tid < 2*(TW+2) + 2*TH) {
        int hh, ww;
        if (tid < (TW+2))            { hh = -1; ww = tid - 1; }
        else if (tid < 2*(TW+2))     { hh = TH; ww = tid - (TW+2) - 1; }
        else if (tid < 2*(TW+2)+TH)  { hh = tid - 2*(TW+2); ww = -1; }
        else                         { hh = tid - (2*(TW+2)+TH); ww = TW; }
        int hg = h0 + hh, wg = w0 + ww;
        float z0 = 0.0f, z1 = 0.0f;
        if ((unsigned)hg < (unsigned)Hh && (unsigned)wg < (unsigned)Ww) {
            int hpix = hg*Ww + wg;
            uint32_t he[2];
            he[0] = (uint32_t)(base_b + hpix);
            he[1] = he[0] + (uint32_t)HW;
            float xa, xb;
            if (SRC_PLANAR) { xa = src[he[0]]; xb = src[he[1]]; }
            else {
                float2 v2 = *reinterpret_cast<const float2*>(src + (size_t)(b*HW + hpix)*8);
                xa = v2.x; xb = v2.y;
            }
            uint32_t hb[2];
            tf_bitsN<2>(k0, k1, he, hb);
            z0 = noised_clip(xa, jax_normal(hb[0])) * 80.0f;
            z1 = noised_clip(xb, jax_normal(hb[1])) * 80.0f;
        }
        sft[hh+1][ww+1] = make_float2(z0, z1);
    }
    __syncthreads();

    const float K0 = g_K[0], K1 = g_K[1];
    float outv[5];

    // ---- image channels: local data-term gradient ----
    {
        float i2p[3] = { i2p4.x, i2p4.y, i2p4.z };
        float yimg[3], diff[3], A = 0.0f;
#pragma unroll
        for (int c = 0; c < 3; c++) {
            float y = noised_clip(xv[2+c], jax_normal(rb[2+c]));
            yimg[c] = y;
            float img1p = (y + 1.0f) * 0.5f;
            float d = img1p - i2p[c];
            diff[c] = d;
            A += d*d;
        }
        float cD = K0 * (0.5f / sqrtf(A + 1e-5f));
#pragma unroll
        for (int c = 0; c < 3; c++) {
            float g = cD * diff[c];
            g = fminf(fmaxf(g, -0.03f), 0.03f);
            outv[2+c] = fminf(fmaxf(fmaf(-10.0f, g, yimg[c]), -1.0f), 1.0f);
        }
    }

    // ---- flow channels: smoothness-term stencil gradient ----
    {
        const int si = ty + 1, sj = tx + 1;
        const bool wp = (w < Ww-1), hp = (h < Hh-1);
        const bool wm = (w > 0),    hm = (h > 0);

        float2 tr  = sft[si][sj+1];     // taps already x80
        float2 td  = sft[si+1][sj];
        float2 tl  = sft[si][sj-1];
        float2 tu  = sft[si-1][sj];
        float2 tdl = sft[si+1][sj-1];
        float2 tur = sft[si-1][sj+1];

        // R at (h, w)
        float dx0 = tr.x - f0, dx1 = tr.y - f1;
        float dy0 = td.x - f0, dy1 = td.y - f1;
        float Sc = (wp ? dx0*dx0 + dx1*dx1 : 0.0f)
                 + (hp ? dy0*dy0 + dy1*dy1 : 0.0f) + 1e-5f;
        float gAc = K1 * (0.5f / sqrtf(Sc));
        gAc += gAc;                                   // exact x2

        // R at (h, w-1)
        float dxl0 = f0 - tl.x,    dxl1 = f1 - tl.y;
        float dyl0 = tdl.x - tl.x, dyl1 = tdl.y - tl.y;
        float Sl = (dxl0*dxl0 + dxl1*dxl1)
                 + (hp ? dyl0*dyl0 + dyl1*dyl1 : 0.0f) + 1e-5f;
        float gAl = K1 * (0.5f / sqrtf(Sl));
        gAl += gAl;

        // R at (h-1, w)
        float dxu0 = tur.x - tu.x, dxu1 = tur.y - tu.y;
        float dyu0 = f0 - tu.x,    dyu1 = f1 - tu.y;
        float Su = (wp ? dxu0*dxu0 + dxu1*dxu1 : 0.0f)
                 + (dyu0*dyu0 + dyu1*dyu1) + 1e-5f;
        float gAu = K1 * (0.5f / sqrtf(Su));
        gAu += gAu;

        float g0 = 0.0f, g1 = 0.0f;
        if (wp) { g0 -= gAc*dx0;  g1 -= gAc*dx1;  }
        if (hp) { g0 -= gAc*dy0;  g1 -= gAc*dy1;  }
        if (wm) { g0 += gAl*dxl0; g1 += gAl*dxl1; }
        if (hm) { g0 += gAu*dyu0; g1 += gAu*dyu1; }
        g0 = __fmul_rn(g0, 80.0f);
        g1 = __fmul_rn(g1, 80.0f);
        g0 = fminf(fmaxf(g0, -0.03f), 0.03f);
        g1 = fminf(fmaxf(g1, -0.03f), 0.03f);

        outv[0] = fminf(fmaxf(fmaf(-10.0f, g0, y0), -1.0f), 1.0f);
        outv[1] = fminf(fmaxf(fmaf(-10.0f, g1, y1), -1.0f), 1.0f);
    }

    // ---- vector store (AoS) ----
    *reinterpret_cast<float4*>(dst + (size_t)bpix*8) =
        make_float4(outv[0], outv[1], outv[2], outv[3]);
    dst[(size_t)bpix*8 + 4] = outv[4];
}

// ---------------- energies: stage 1 (per-block partials) ----------------
__global__ void __launch_bounds__(256)
energy_partial(const float* __restrict__ buf, const float* __restrict__ target1,
               const float* __restrict__ input1)
{
    const int mode = blockIdx.z, b = blockIdx.y, blk = blockIdx.x;
    const int t = threadIdx.x;
    const int PPB = HW / EBLK;   // 2048
    float sd = 0.0f, ss = 0.0f;

    for (int i = t; i < PPB; i += 256) {
        int pix = blk*PPB + i;
        int h = pix / Ww, w = pix - h*Ww;
        int bpix = b*HW + pix;

        // data term
        float A = 0.0f;
#pragma unroll
        for (int c = 0; c < 3; c++) {
            float img2p = g_img2p[(size_t)bpix*4 + c];
            float img1p;
            if (mode == 0) {
                float i1 = input1[(b*3+c)*HW + pix];
                img1p = ((i1*2.0f - 1.0f) + 1.0f) * 0.5f;
            } else {
                img1p = (buf[(size_t)bpix*8 + 2 + c] + 1.0f) * 0.5f;
            }
            float d = img1p - img2p;
            A += d*d;
        }
        sd += sqrtf(A + 1e-5f);

        // smoothness term
        float Bx = 0.0f, By = 0.0f;
#pragma unroll
        for (int c = 0; c < 2; c++) {
            float f, fr = 0.0f, fd = 0.0f;
            if (mode == 0) {
                const float* tp = target1 + (b*2+c)*HW;
                f = (tp[pix] / 80.0f) * 80.0f;
                if (w < Ww-1) fr = (tp[pix+1]  / 80.0f) * 80.0f;
                if (h < Hh-1) fd = (tp[pix+Ww] / 80.0f) * 80.0f;
            } else {
                f = buf[(size_t)bpix*8 + c] * 80.0f;
                if (w < Ww-1) fr = buf[(size_t)(bpix+1)*8  + c] * 80.0f;
                if (h < Hh-1) fd = buf[(size_t)(bpix+Ww)*8 + c] * 80.0f;
            }
            if (w < Ww-1) { float dx = fr - f; Bx += dx*dx; }
            if (h < Hh-1) { float dy = fd - f; By += dy*dy; }
        }
        ss += sqrtf(Bx + By + 1e-5f);
    }

    __shared__ float rd[256], rs[256];
    rd[t] = sd; rs[t] = ss;
    __syncthreads();
    for (int s = 128; s > 0; s >>= 1) {
        if (t < s) { rd[t] += rd[t+s]; rs[t] += rs[t+s]; }
        __syncthreads();
    }
    if (t == 0) {
        int o = (mode*Bb + b)*EBLK + blk;
        g_part[2*o]   = rd[0];
        g_part[2*o+1] = rs[0];
    }
}

// ---------------- energies: stage 2 ----------------
__global__ void energy_final(const float* __restrict__ lw, float* __restrict__ out)
{
    int t = threadIdx.x;
    if (t >= 16) return;
    float sd = 0.0f, ss = 0.0f;
    for (int k = 0; k < EBLK; k++) {
        sd += g_part[2*(t*EBLK + k)];
        ss += g_part[2*(t*EBLK + k) + 1];
    }
    out[t] = (expf(lw[0])*sd + expf(lw[1])*ss) / 196608.0f;
}

// ---------------- output formatting (reads AoS) ----------------
__global__ void __launch_bounds__(512)
format_kernel(const float* __restrict__ buf, float* __restrict__ out)
{
    int i = blockIdx.x*512 + threadIdx.x;   // over Bb*HW pixels
    if (i >= Bb*HW) return;
    int b = i / HW;
    int pix = i - b*HW;
    float4 v4 = *reinterpret_cast<const float4*>(buf + (size_t)i*8);
    float  v5 = buf[(size_t)i*8 + 4];
    out[16 + (b*2 + 0)*HW + pix] = v4.x * 80.0f;
    out[16 + (b*2 + 1)*HW + pix] = v4.y * 80.0f;
    out[16 + Bb*2*HW + (b*3 + 0)*HW + pix] = (v4.z + 1.0f) * 0.5f;
    out[16 + Bb*2*HW + (b*3 + 1)*HW + pix] = (v4.w + 1.0f) * 0.5f;
    out[16 + Bb*2*HW + (b*3 + 2)*HW + pix] = (v5   + 1.0f) * 0.5f;
}

// ---------------- host threefry (per-step keys) ----------------
static inline uint32_t h_rotl(uint32_t x, int d) { return (x << d) | (x >> (32 - d)); }
static void h_tf(uint32_t k0, uint32_t k1, uint32_t c0, uint32_t c1,
                 uint32_t& o0, uint32_t& o1)
{
    uint32_t ks2 = k0 ^ k1 ^ 0x1BD11BDAu;
    uint32_t x0 = c0 + k0, x1 = c1 + k1;
#define HR(r) { x0 += x1; x1 = h_rotl(x1, r); x1 ^= x0; }
    HR(13) HR(15) HR(26) HR(6)
    x0 += k1;  x1 += ks2 + 1u;
    HR(17) HR(29) HR(16) HR(24)
    x0 += ks2; x1 += k0 + 2u;
    HR(13) HR(15) HR(26) HR(6)
    x0 += k0;  x1 += k1 + 3u;
    HR(17) HR(29) HR(16) HR(24)
    x0 += k1;  x1 += ks2 + 4u;
    HR(13) HR(15) HR(26) HR(6)
    x0 += ks2; x1 += k0 + 5u;
#undef HR
    o0 = x0; o1 = x1;
}

extern "C" void kernel_launch(void* const* d_in, const int* in_sizes, int n_in,
                              void* d_out, int out_size)
{
    const float* target1 = (const float*)d_in[0];
    const float* input1  = (const float*)d_in[1];
    const float* input2  = (const float*)d_in[2];
    const float* init    = (const float*)d_in[3];
    const float* lw      = (const float*)d_in[4];
    float* out = (float*)d_out;

    float *pA, *pB;
    cudaGetSymbolAddress((void**)&pA, g_bufA);
    cudaGetSymbolAddress((void**)&pB, g_bufB);

    k_init<<<1, 1>>>(lw);
    prep_img2<<<(NIMG + 511)/512, 512>>>(input2);

    dim3 grid(Ww/TW, Hh/TH, Bb);   // (16, 24, 8)

    // step 0: planar src (init) -> AoS pA
    {
        uint32_t o0, o1;
        h_tf(0u, 1u, 0u, 0u, o0, o1);
        step_kernel<true><<<grid, TW*TH>>>(init, pA, o0, o1);
    }
    const float* cur = pA;
    for (int t = 1; t < NSTEPS; t++) {
        uint32_t o0, o1;
        h_tf(0u, 1u, 0u, (uint32_t)t, o0, o1);
        float* dst = (t & 1) ? pB : pA;
        step_kernel<false><<<grid, TW*TH>>>(cur, dst, o0, o1);
        cur = dst;
    }

    energy_partial<<<dim3(EBLK, Bb, 2), 256>>>(cur, target1, input1);
    energy_final<<<1, 32>>>(lw, out);
    format_kernel<<<(Bb*HW + 511)/512, 512>>>(cur, out);
}

// round 13
// speedup vs baseline: 1.4081x; 1.0601x over previous
#include <cuda_runtime.h>
#include <cstdint>

#define Hh 384
#define Ww 512
#define Bb 8
#define HW (Hh*Ww)              // 196608
#define NIMG  (Bb*3*HW)         // 4718592
#define NSTEPS 200
#define TW 32
#define TH 16
#define EBLK 96

// ---------------- static scratch (no allocation allowed) ----------------
__device__ float2 g_flowA[Bb*HW];
__device__ float2 g_flowB[Bb*HW];
__device__ float4 g_imgA[Bb*HW];          // .xyz used
__device__ float4 g_imgB[Bb*HW];
__device__ float4 g_j[Bb*HW];             // j_c = 0.5 - img2p_c  (.xyz used)
__device__ float  g_K[2];                 // K0/2, K1  (pre-divided by H*W)
__device__ float  g_part[2*Bb*EBLK*2];

// ---------------- threefry2x32, JAX-exact, c0 = 0, N independent lanes ----
template<int N>
__device__ __forceinline__ void tf_bitsN(uint32_t k0, uint32_t k1,
                                         const uint32_t* c, uint32_t* r)
{
    const uint32_t ks2 = k0 ^ k1 ^ 0x1BD11BDAu;
    uint32_t x0[N], x1[N];
#pragma unroll
    for (int i = 0; i < N; i++) { x0[i] = k0; x1[i] = c[i] + k1; }

    auto rnd = [&](int rot) {
#pragma unroll
        for (int i = 0; i < N; i++) {
            x0[i] += x1[i];
            x1[i] = __funnelshift_l(x1[i], x1[i], rot);
            x1[i] ^= x0[i];
        }
    };
    auto inj = [&](uint32_t i0, uint32_t i1) {
#pragma unroll
        for (int i = 0; i < N; i++) { x0[i] += i0; x1[i] += i1; }
    };

    rnd(13); rnd(15); rnd(26); rnd(6);  inj(k1,  ks2 + 1u);
    rnd(17); rnd(29); rnd(16); rnd(24); inj(ks2, k0  + 2u);
    rnd(13); rnd(15); rnd(26); rnd(6);  inj(k0,  k1  + 3u);
    rnd(17); rnd(29); rnd(16); rnd(24); inj(k1,  ks2 + 4u);
    rnd(13); rnd(15); rnd(26); rnd(6);  inj(ks2, k0  + 5u);

#pragma unroll
    for (int i = 0; i < N; i++) r[i] = x0[i] ^ x1[i];
}

// ------------- jax.random.normal: uniform(lo,1) -> sqrt(2)*erfinv --------
__device__ __forceinline__ float jax_normal(uint32_t bits)
{
    const float lo = __uint_as_float(0xBF7FFFFFu);      // nextafter(-1, 0)
    float f = __uint_as_float((bits >> 9) | 0x3F800000u) - 1.0f;  // [0,1)
    float u = fmaxf(lo, f * 2.0f + lo);

    float w = -__logf(fmaf(-u, u, 1.0f));
    float p;
    if (w < 5.0f) {
        w = w - 2.5f;
        p =          2.81022636e-08f;
        p = p * w +  3.43273939e-07f;
        p = p * w + -3.5233877e-06f;
        p = p * w + -4.39150654e-06f;
        p = p * w +  0.00021858087f;
        p = p * w + -0.00125372503f;
        p = p * w + -0.00417768164f;
        p = p * w +  0.246640727f;
        p = p * w +  1.50140941f;
    } else {
        w = sqrtf(w) - 3.0f;
        p =         -0.000200214257f;
        p = p * w +  0.000100950558f;
        p = p * w +  0.00134934322f;
        p = p * w + -0.00367342844f;
        p = p * w +  0.00573950773f;
        p = p * w + -0.0076224613f;
        p = p * w +  0.00943887047f;
        p = p * w +  1.00167406f;
        p = p * w +  2.83297682f;
    }
    return 1.41421356237309515f * (p * u);
}

__device__ __forceinline__ float noised_clip(float x, float n)
{
    return fminf(fmaxf(fmaf(0.05f, n, x), -1.0f), 1.0f);
}

// ---------------- one-time prep: K and j ----------------
__global__ void k_init(const float* __restrict__ lw)
{
    g_K[0] = 0.5f * expf(lw[0]) / 196608.0f;   // K0/2
    g_K[1] = expf(lw[1]) / 196608.0f;          // K1 (0.5 and x2 cancel)
}

__global__ void __launch_bounds__(512)
prep_j(const float* __restrict__ input2)
{
    int i = blockIdx.x*512 + threadIdx.x;
    if (i >= NIMG) return;
    int b   = i / (3*HW);
    int r   = i - b*3*HW;
    int c   = r / HW;
    int pix = r - c*HW;
    float i2   = input2[i];
    float i2p  = ((i2*2.0f - 1.0f) + 1.0f) * 0.5f;
    reinterpret_cast<float*>(&g_j[b*HW + pix])[c] = 0.5f - i2p;
}

// ---------------- fused Langevin step: noise + analytic grad + update ----
template<bool SRC_PLANAR>
__global__ void __launch_bounds__(TW*TH, 3)
step_kernel(const float* __restrict__ srcp,
            const float2* __restrict__ srcf, const float4* __restrict__ srci,
            float2* __restrict__ dstf, float4* __restrict__ dsti,
            uint32_t k0, uint32_t k1)
{
    __shared__ float2 sft[TH+2][TW+2];     // SCALED (x80) noised flow, 1-halo

    const int b  = blockIdx.z;
    const int h0 = blockIdx.y * TH;
    const int w0 = blockIdx.x * TW;
    const int tid = threadIdx.x;
    const int tx = tid & (TW-1), ty = tid >> 5;
    const int base_b = b * 5 * HW;

    const int h = h0 + ty, w = w0 + tx;
    const int pix  = h*Ww + w;
    const int bpix = b*HW + pix;

    // ---- counters = JAX planar flat indices ----
    uint32_t ce[5];
    ce[0] = (uint32_t)(base_b + pix);
#pragma unroll
    for (int i = 1; i < 5; i++) ce[i] = ce[0] + (uint32_t)(i*HW);

    // ---- front-batched loads ----
    float xv[5];
    if (SRC_PLANAR) {
#pragma unroll
        for (int i = 0; i < 5; i++) xv[i] = srcp[ce[i]];
    } else {
        float2 vf = srcf[bpix];
        float4 vi = srci[bpix];
        xv[0] = vf.x; xv[1] = vf.y; xv[2] = vi.x; xv[3] = vi.y; xv[4] = vi.z;
    }
    float4 j4 = g_j[bpix];

    uint32_t rb[5];
    tf_bitsN<5>(k0, k1, ce, rb);

    float y0 = noised_clip(xv[0], jax_normal(rb[0]));
    float y1 = noised_clip(xv[1], jax_normal(rb[1]));
    float f0 = y0*80.0f, f1 = y1*80.0f;
    sft[ty+1][tx+1] = make_float2(f0, f1);

    // ---- halo ring: 100 cells, threads 0..99 ----
    if (tid < 2*(TW+2) + 2*TH) {
        int hh, ww;
        if (tid < (TW+2))            { hh = -1; ww = tid - 1; }
        else if (tid < 2*(TW+2))     { hh = TH; ww = tid - (TW+2) - 1; }
        else if (tid < 2*(TW+2)+TH)  { hh = tid - 2*(TW+2); ww = -1; }
        else                         { hh = tid - (2*(TW+2)+TH); ww = TW; }
        int hg = h0 + hh, wg = w0 + ww;
        float z0 = 0.0f, z1 = 0.0f;
        if ((unsigned)hg < (unsigned)Hh && (unsigned)wg < (unsigned)Ww) {
            int hpix = hg*Ww + wg;
            uint32_t he[2];
            he[0] = (uint32_t)(base_b + hpix);
            he[1] = he[0] + (uint32_t)HW;
            float xa, xb;
            if (SRC_PLANAR) { xa = srcp[he[0]]; xb = srcp[he[1]]; }
            else {
                float2 v2 = srcf[b*HW + hpix];
                xa = v2.x; xb = v2.y;
            }
            uint32_t hb[2];
            tf_bitsN<2>(k0, k1, he, hb);
            z0 = noised_clip(xa, jax_normal(hb[0])) * 80.0f;
            z1 = noised_clip(xb, jax_normal(hb[1])) * 80.0f;
        }
        sft[hh+1][ww+1] = make_float2(z0, z1);
    }
    __syncthreads();

    const float K0h = g_K[0], K1 = g_K[1];

    // ---- image channels: local data-term gradient ----
    float oi0, oi1, oi2;
    {
        float jv[3] = { j4.x, j4.y, j4.z };
        float yimg[3], diff[3], A = 0.0f;
#pragma unroll
        for (int c = 0; c < 3; c++) {
            float y = noised_clip(xv[2+c], jax_normal(rb[2+c]));
            yimg[c] = y;
            float d = fmaf(0.5f, y, jv[c]);     // (y+1)/2 - img2p  (1 ulp)
            diff[c] = d;
            A += d*d;
        }
        float cD = K0h * rsqrtf(A + 1e-5f);
        float o[3];
#pragma unroll
        for (int c = 0; c < 3; c++) {
            float g = cD * diff[c];
            g = fminf(fmaxf(g, -0.03f), 0.03f);
            o[c] = fminf(fmaxf(fmaf(-10.0f, g, yimg[c]), -1.0f), 1.0f);
        }
        oi0 = o[0]; oi1 = o[1]; oi2 = o[2];
    }

    // ---- flow channels: smoothness-term stencil gradient ----
    float of0, of1;
    {
        const int si = ty + 1, sj = tx + 1;
        const bool wp = (w < Ww-1), hp = (h < Hh-1);
        const bool wm = (w > 0),    hm = (h > 0);

        float2 tr  = sft[si][sj+1];     // taps already x80
        float2 td  = sft[si+1][sj];
        float2 tl  = sft[si][sj-1];
        float2 tu  = sft[si-1][sj];
        float2 tdl = sft[si+1][sj-1];
        float2 tur = sft[si-1][sj+1];

        // R at (h, w)
        float dx0 = tr.x - f0, dx1 = tr.y - f1;
        float dy0 = td.x - f0, dy1 = td.y - f1;
        float Sc = (wp ? dx0*dx0 + dx1*dx1 : 0.0f)
                 + (hp ? dy0*dy0 + dy1*dy1 : 0.0f) + 1e-5f;
        float gAc = K1 * rsqrtf(Sc);            // = 2*K1*(0.5/sqrt)

        // R at (h, w-1)
        float dxl0 = f0 - tl.x,    dxl1 = f1 - tl.y;
        float dyl0 = tdl.x - tl.x, dyl1 = tdl.y - tl.y;
        float Sl = (dxl0*dxl0 + dxl1*dxl1)
                 + (hp ? dyl0*dyl0 + dyl1*dyl1 : 0.0f) + 1e-5f;
        float gAl = K1 * rsqrtf(Sl);

        // R at (h-1, w)
        float dxu0 = tur.x - tu.x, dxu1 = tur.y - tu.y;
        float dyu0 = f0 - tu.x,    dyu1 = f1 - tu.y;
        float Su = (wp ? dxu0*dxu0 + dxu1*dxu1 : 0.0f)
                 + (dyu0*dyu0 + dyu1*dyu1) + 1e-5f;
        float gAu = K1 * rsqrtf(Su);

        float g0 = 0.0f, g1 = 0.0f;
        if (wp) { g0 -= gAc*dx0;  g1 -= gAc*dx1;  }
        if (hp) { g0 -= gAc*dy0;  g1 -= gAc*dy1;  }
        if (wm) { g0 += gAl*dxl0; g1 += gAl*dxl1; }
        if (hm) { g0 += gAu*dyu0; g1 += gAu*dyu1; }
        g0 = __fmul_rn(g0, 80.0f);
        g1 = __fmul_rn(g1, 80.0f);
        g0 = fminf(fmaxf(g0, -0.03f), 0.03f);
        g1 = fminf(fmaxf(g1, -0.03f), 0.03f);

        of0 = fminf(fmaxf(fmaf(-10.0f, g0, y0), -1.0f), 1.0f);
        of1 = fminf(fmaxf(fmaf(-10.0f, g1, y1), -1.0f), 1.0f);
    }

    // ---- vector stores ----
    dstf[bpix] = make_float2(of0, of1);
    dsti[bpix] = make_float4(oi0, oi1, oi2, 0.0f);
}

// ---------------- energies: stage 1 (per-block partials) ----------------
// Energy math follows exact reference fp ordering (runs once; feeds output).
__global__ void __launch_bounds__(256)
energy_partial(const float2* __restrict__ buff, const float4* __restrict__ bufi,
               const float* __restrict__ target1, const float* __restrict__ input1,
               const float* __restrict__ input2)
{
    const int mode = blockIdx.z, b = blockIdx.y, blk = blockIdx.x;
    const int t = threadIdx.x;
    const int PPB = HW / EBLK;   // 2048
    float sd = 0.0f, ss = 0.0f;

    for (int i = t; i < PPB; i += 256) {
        int pix = blk*PPB + i;
        int h = pix / Ww, w = pix - h*Ww;
        int bpix = b*HW + pix;

        // data term
        float A = 0.0f;
        float4 vi = bufi[bpix];
        float iv[3] = { vi.x, vi.y, vi.z };
#pragma unroll
        for (int c = 0; c < 3; c++) {
            float i2    = input2[(b*3+c)*HW + pix];
            float img2p = ((i2*2.0f - 1.0f) + 1.0f) * 0.5f;
            float img1p;
            if (mode == 0) {
                float i1 = input1[(b*3+c)*HW + pix];
                img1p = ((i1*2.0f - 1.0f) + 1.0f) * 0.5f;
            } else {
                img1p = (iv[c] + 1.0f) * 0.5f;
            }
            float d = img1p - img2p;
            A += d*d;
        }
        sd += sqrtf(A + 1e-5f);

        // smoothness term
        float Bx = 0.0f, By = 0.0f;
#pragma unroll
        for (int c = 0; c < 2; c++) {
            float f, fr = 0.0f, fd = 0.0f;
            if (mode == 0) {
                const float* tp = target1 + (b*2+c)*HW;
                f = (tp[pix] / 80.0f) * 80.0f;
                if (w < Ww-1) fr = (tp[pix+1]  / 80.0f) * 80.0f;
                if (h < Hh-1) fd = (tp[pix+Ww] / 80.0f) * 80.0f;
            } else {
                f = (c ? buff[bpix].y : buff[bpix].x) * 80.0f;
                if (w < Ww-1) fr = (c ? buff[bpix+1].y  : buff[bpix+1].x)  * 80.0f;
                if (h < Hh-1) fd = (c ? buff[bpix+Ww].y : buff[bpix+Ww].x) * 80.0f;
            }
            if (w < Ww-1) { float dx = fr - f; Bx += dx*dx; }
            if (h < Hh-1) { float dy = fd - f; By += dy*dy; }
        }
        ss += sqrtf(Bx + By + 1e-5f);
    }

    __shared__ float rd[256], rs[256];
    rd[t] = sd; rs[t] = ss;
    __syncthreads();
    for (int s = 128; s > 0; s >>= 1) {
        if (t < s) { rd[t] += rd[t+s]; rs[t] += rs[t+s]; }
        __syncthreads();
    }
    if (t == 0) {
        int o = (mode*Bb + b)*EBLK + blk;
        g_part[2*o]   = rd[0];
        g_part[2*o+1] = rs[0];
    }
}

// ---------------- energies: stage 2 ----------------
__global__ void energy_final(const float* __restrict__ lw, float* __restrict__ out)
{
    int t = threadIdx.x;
    if (t >= 16) return;
    float sd = 0.0f, ss = 0.0f;
    for (int k = 0; k < EBLK; k++) {
        sd += g_part[2*(t*EBLK + k)];
        ss += g_part[2*(t*EBLK + k) + 1];
    }
    out[t] = (expf(lw[0])*sd + expf(lw[1])*ss) / 196608.0f;
}

// ---------------- output formatting ----------------
__global__ void __launch_bounds__(512)
format_kernel(const float2* __restrict__ buff, const float4* __restrict__ bufi,
              float* __restrict__ out)
{
    int i = blockIdx.x*512 + threadIdx.x;   // over Bb*HW pixels
    if (i >= Bb*HW) return;
    int b = i / HW;
    int pix = i - b*HW;
    float2 vf = buff[i];
    float4 vi = bufi[i];
    out[16 + (b*2 + 0)*HW + pix] = vf.x * 80.0f;
    out[16 + (b*2 + 1)*HW + pix] = vf.y * 80.0f;
    out[16 + Bb*2*HW + (b*3 + 0)*HW + pix] = (vi.x + 1.0f) * 0.5f;
    out[16 + Bb*2*HW + (b*3 + 1)*HW + pix] = (vi.y + 1.0f) * 0.5f;
    out[16 + Bb*2*HW + (b*3 + 2)*HW + pix] = (vi.z + 1.0f) * 0.5f;
}

// ---------------- host threefry (per-step keys) ----------------
static inline uint32_t h_rotl(uint32_t x, int d) { return (x << d) | (x >> (32 - d)); }
static void h_tf(uint32_t k0, uint32_t k1, uint32_t c0, uint32_t c1,
                 uint32_t& o0, uint32_t& o1)
{
    uint32_t ks2 = k0 ^ k1 ^ 0x1BD11BDAu;
    uint32_t x0 = c0 + k0, x1 = c1 + k1;
#define HR(r) { x0 += x1; x1 = h_rotl(x1, r); x1 ^= x0; }
    HR(13) HR(15) HR(26) HR(6)
    x0 += k1;  x1 += ks2 + 1u;
    HR(17) HR(29) HR(16) HR(24)
    x0 += ks2; x1 += k0 + 2u;
    HR(13) HR(15) HR(26) HR(6)
    x0 += k0;  x1 += k1 + 3u;
    HR(17) HR(29) HR(16) HR(24)
    x0 += k1;  x1 += ks2 + 4u;
    HR(13) HR(15) HR(26) HR(6)
    x0 += ks2; x1 += k0 + 5u;
#undef HR
    o0 = x0; o1 = x1;
}

extern "C" void kernel_launch(void* const* d_in, const int* in_sizes, int n_in,
                              void* d_out, int out_size)
{
    const float* target1 = (const float*)d_in[0];
    const float* input1  = (const float*)d_in[1];
    const float* input2  = (const float*)d_in[2];
    const float* init    = (const float*)d_in[3];
    const float* lw      = (const float*)d_in[4];
    float* out = (float*)d_out;

    float2 *fA, *fB; float4 *iA, *iB;
    cudaGetSymbolAddress((void**)&fA, g_flowA);
    cudaGetSymbolAddress((void**)&fB, g_flowB);
    cudaGetSymbolAddress((void**)&iA, g_imgA);
    cudaGetSymbolAddress((void**)&iB, g_imgB);

    k_init<<<1, 1>>>(lw);
    prep_j<<<(NIMG + 511)/512, 512>>>(input2);

    dim3 grid(Ww/TW, Hh/TH, Bb);   // (16, 24, 8)

    // step 0: planar src (init) -> split buffers A
    {
        uint32_t o0, o1;
        h_tf(0u, 1u, 0u, 0u, o0, o1);
        step_kernel<true><<<grid, TW*TH>>>(init, nullptr, nullptr, fA, iA, o0, o1);
    }
    const float2* cf = fA; const float4* ci = iA;
    for (int t = 1; t < NSTEPS; t++) {
        uint32_t o0, o1;
        h_tf(0u, 1u, 0u, (uint32_t)t, o0, o1);
        float2* df = (t & 1) ? fB : fA;
        float4* di = (t & 1) ? iB : iA;
        step_kernel<false><<<grid, TW*TH>>>(nullptr, cf, ci, df, di, o0, o1);
        cf = df; ci = di;
    }

    energy_partial<<<dim3(EBLK, Bb, 2), 256>>>(cf, ci, target1, input1, input2);
    energy_final<<<1, 32>>>(lw, out);
    format_kernel<<<(Bb*HW + 511)/512, 512>>>(cf, ci, out);
}